// round 13
// baseline (speedup 1.0000x reference)
#include <cuda_runtime.h>
#include <cstdint>

// ---------------------------------------------------------------------------
// CNN3_FPB: patch-GEMM -> 3x conv1d (im2col GEMM) -> FC, plus branch MLP.
// All stages expressed as fused im2col SGEMM (fp32, float4 loads,
// register-staged double-buffered smem pipeline, 1 barrier per k-tile).
// Activations stored [b][pos][ch] so im2col gathers are contiguous.
// ---------------------------------------------------------------------------

#define BATCH 2048

// scratch (device globals: allocation-free per harness rules; zero-initialized)
__device__ float g_base[BATCH * 64];
__device__ float g_h1[(size_t)BATCH * 255 * 64];    // patch out, [b][pos][64]
__device__ float g_h2[(size_t)BATCH * 255 * 128];   // conv1 out, [b][pos][128]
__device__ float g_h3[(size_t)BATCH * 128 * 256];   // conv2 out, [b][pos][256]
__device__ float g_z[(size_t)BATCH * 16640];        // concat: conv3 (ch-major 16384) + f (256)
__device__ float g_f1[BATCH * 64];
__device__ float g_f2[BATCH * 128];
__device__ float g_fc1[(size_t)BATCH * 1024];
__device__ float g_W1t[128 * 192];
__device__ float g_W2t[256 * 384];
__device__ float g_W3t[256 * 768];
__device__ float g_Wp0[64 * 64];
__device__ float g_Wp1[64 * 64];
__device__ float g_zero[1024];                       // stays zero

// ---------------------------------------------------------------------------
// Weight reorder: (Cout, Cin, Kw) -> Wt[o][kpos*Cin + ci]
// ---------------------------------------------------------------------------
__global__ void reorder_w_kernel(const float* __restrict__ W, float* __restrict__ Wt,
                                 int Cout, int Cin, int Kw) {
    int idx = blockIdx.x * blockDim.x + threadIdx.x;
    int total = Cout * Cin * Kw;
    if (idx >= total) return;
    int kp = idx % Kw;
    int ci = (idx / Kw) % Cin;
    int o  = idx / (Kw * Cin);
    Wt[(size_t)o * (Cin * Kw) + kp * Cin + ci] = W[idx];
}

// Wp (64,64,2) -> Wp0[p][i], Wp1[p][i]
__global__ void extract_wp_kernel(const float* __restrict__ Wp,
                                  float* __restrict__ W0, float* __restrict__ W1) {
    int idx = blockIdx.x * blockDim.x + threadIdx.x;
    if (idx >= 64 * 64) return;
    W0[idx] = Wp[idx * 2 + 0];
    W1[idx] = Wp[idx * 2 + 1];
}

// ---------------------------------------------------------------------------
// Generic fused im2col SGEMM with 2-stage smem pipeline.
//   rows r = b*LOUT + c ;  cols n < N ;  K = CIN*KW
//   A element (r, k): kpos = k/CIN, ci = k%CIN, inpos = c*STRIDE - PADL + kpos
//                     value = A[b*IN_STRIDE + inpos*CIN + ci]  (0 if OOB)
//   Wt is [n][k] row-major.
//   Epilogue: + bias[n] (+ rowbias[b*N+n]) (+relu); store [b][c][n] or
//   transposed [b][n*LOUT+c] (conv3 -> concat).
// 256 threads, 16x16 layout, TM=BM/16 x TN=BN/16 per thread, BK=16.
// Pipeline: fetch tile t+1 into regs (LDG in flight during compute), compute
// tile t from smem[cur], store regs -> smem[cur^1], ONE barrier, swap.
// Correctness of the single barrier: writes target the buffer whose readers
// finished before the PREVIOUS barrier; reads of cur are fenced before the
// next overwrite by THIS barrier.
// ---------------------------------------------------------------------------
template<int BM, int BN, int BK, int N, int K, int LIN, int CIN,
         int STRIDE, int PADL, int LOUT, int IN_STRIDE, int OUT_STRIDE,
         bool RELU, bool TRANS_STORE, bool HAS_ROWBIAS>
__global__ __launch_bounds__(256, 2)
void gemm_kernel(const float* __restrict__ A,
                 const float* __restrict__ Wt,
                 const float* __restrict__ bias,
                 const float* __restrict__ rowbias,
                 float* __restrict__ out)
{
    constexpr int TM = BM / 16, TN = BN / 16;
    constexpr int KV = BK / 4;                 // float4 chunks along k
    constexpr int AIT = (BM * KV) / 256;       // A float4 loads per thread
    constexpr int BIT = (BN * KV) / 256;       // B float4 loads per thread
    constexpr int NT = K / BK;                 // k tiles
    static_assert(CIN % 4 == 0 && K % 4 == 0 && BK % 4 == 0, "vec preconds");
    static_assert(TM % 4 == 0 && TN % 4 == 0, "frag vec preconds");
    static_assert((BM * KV) % 256 == 0 && (BN * KV) % 256 == 0, "tile loop preconds");
    static_assert(K % BK == 0, "k tiling");
    __shared__ float As[2][BK][BM + 4];
    __shared__ float Bs[2][BK][BN + 4];
    const int tid = threadIdx.x;
    const int ty = tid >> 4, tx = tid & 15;
    const int m0 = blockIdx.x * BM;
    const int n0 = blockIdx.y * BN;

    float4 aReg[AIT], bReg[BIT];

    // --- fetch tile k0 into registers ---
    auto fetchA = [&](int k0) {
#pragma unroll
        for (int it = 0; it < AIT; it++) {
            int v = it * 256 + tid;
            int mm = v / KV;
            int kk = (v - mm * KV) * 4;
            int row = m0 + mm;
            int b = row / LOUT;
            int c = row - b * LOUT;
            int k = k0 + kk;
            int kpos = k / CIN;
            int ci = k - kpos * CIN;
            int inpos = c * STRIDE - PADL + kpos;
            float4 val = make_float4(0.f, 0.f, 0.f, 0.f);
            if (inpos >= 0 && inpos < LIN)
                val = *reinterpret_cast<const float4*>(
                    &A[(size_t)b * IN_STRIDE + (size_t)inpos * CIN + ci]);
            aReg[it] = val;
        }
    };
    auto fetchB = [&](int k0) {
#pragma unroll
        for (int it = 0; it < BIT; it++) {
            int v = it * 256 + tid;
            int nn = v / KV;
            int kk = (v - nn * KV) * 4;
            bReg[it] = *reinterpret_cast<const float4*>(
                &Wt[(size_t)(n0 + nn) * K + (k0 + kk)]);
        }
    };
    // --- store staged registers into smem buffer s ---
    auto stageStore = [&](int s) {
#pragma unroll
        for (int it = 0; it < AIT; it++) {
            int v = it * 256 + tid;
            int mm = v / KV;
            int kk = (v - mm * KV) * 4;
            As[s][kk + 0][mm] = aReg[it].x;
            As[s][kk + 1][mm] = aReg[it].y;
            As[s][kk + 2][mm] = aReg[it].z;
            As[s][kk + 3][mm] = aReg[it].w;
        }
#pragma unroll
        for (int it = 0; it < BIT; it++) {
            int v = it * 256 + tid;
            int nn = v / KV;
            int kk = (v - nn * KV) * 4;
            Bs[s][kk + 0][nn] = bReg[it].x;
            Bs[s][kk + 1][nn] = bReg[it].y;
            Bs[s][kk + 2][nn] = bReg[it].z;
            Bs[s][kk + 3][nn] = bReg[it].w;
        }
    };

    float acc[TM][TN];
#pragma unroll
    for (int i = 0; i < TM; i++)
#pragma unroll
        for (int j = 0; j < TN; j++) acc[i][j] = 0.f;

    // prologue: tile 0 -> buffer 0
    fetchA(0);
    fetchB(0);
    stageStore(0);
    __syncthreads();

    int cur = 0;
    for (int t = 0; t < NT; t++) {
        // prefetch next tile into registers (LDG latency overlapped by compute)
        if (t + 1 < NT) {
            fetchA((t + 1) * BK);
            fetchB((t + 1) * BK);
        }
        // compute on smem[cur]
#pragma unroll
        for (int kk = 0; kk < BK; kk++) {
            float a[TM], bb[TN];
#pragma unroll
            for (int i = 0; i < TM; i += 4)
                *reinterpret_cast<float4*>(&a[i]) =
                    *reinterpret_cast<const float4*>(&As[cur][kk][ty * TM + i]);
#pragma unroll
            for (int j = 0; j < TN; j += 4)
                *reinterpret_cast<float4*>(&bb[j]) =
                    *reinterpret_cast<const float4*>(&Bs[cur][kk][tx * TN + j]);
#pragma unroll
            for (int i = 0; i < TM; i++)
#pragma unroll
                for (int j = 0; j < TN; j++)
                    acc[i][j] = fmaf(a[i], bb[j], acc[i][j]);
        }
        if (t + 1 < NT) {
            stageStore(cur ^ 1);
            __syncthreads();
            cur ^= 1;
        }
    }

    // --- epilogue ---
#pragma unroll
    for (int i = 0; i < TM; i++) {
        int row = m0 + ty * TM + i;
        int b = row / LOUT;
        int c = row - b * LOUT;
#pragma unroll
        for (int j = 0; j < TN; j++) {
            int n = n0 + tx * TN + j;
            float v = acc[i][j] + bias[n];
            if (HAS_ROWBIAS) v += rowbias[b * N + n];
            if (RELU) v = fmaxf(v, 0.f);
            if (TRANS_STORE)
                out[(size_t)b * OUT_STRIDE + (size_t)n * LOUT + c] = v;
            else
                out[(size_t)b * OUT_STRIDE + (size_t)c * N + n] = v;
        }
    }
}

// ---------------------------------------------------------------------------
// FC2: (B,1024) @ (2,1024)^T + b -> (B,2). One block per batch row.
// Warp-shuffle butterfly within warps, tiny smem combine across 8 warps.
// ---------------------------------------------------------------------------
__global__ __launch_bounds__(256)
void fc2_kernel(const float* __restrict__ in, const float* __restrict__ W,
                const float* __restrict__ bias, float* __restrict__ out) {
    int b = blockIdx.x;
    float a0 = 0.f, a1 = 0.f;
    for (int k = threadIdx.x * 4; k < 1024; k += 256 * 4) {
        float4 v = *reinterpret_cast<const float4*>(&in[(size_t)b * 1024 + k]);
        float4 w0 = *reinterpret_cast<const float4*>(&W[k]);
        float4 w1 = *reinterpret_cast<const float4*>(&W[1024 + k]);
        a0 = fmaf(v.x, w0.x, fmaf(v.y, w0.y, fmaf(v.z, w0.z, fmaf(v.w, w0.w, a0))));
        a1 = fmaf(v.x, w1.x, fmaf(v.y, w1.y, fmaf(v.z, w1.z, fmaf(v.w, w1.w, a1))));
    }
#pragma unroll
    for (int off = 16; off > 0; off >>= 1) {
        a0 += __shfl_xor_sync(0xFFFFFFFFu, a0, off);
        a1 += __shfl_xor_sync(0xFFFFFFFFu, a1, off);
    }
    __shared__ float s0[8], s1[8];
    int wid = threadIdx.x >> 5, lid = threadIdx.x & 31;
    if (lid == 0) { s0[wid] = a0; s1[wid] = a1; }
    __syncthreads();
    if (threadIdx.x == 0) {
        float t0 = 0.f, t1 = 0.f;
#pragma unroll
        for (int w = 0; w < 8; w++) { t0 += s0[w]; t1 += s1[w]; }
        out[b * 2 + 0] = t0 + bias[0];
        out[b * 2 + 1] = t1 + bias[1];
    }
}

// ---------------------------------------------------------------------------
extern "C" void kernel_launch(void* const* d_in, const int* /*in_sizes*/, int /*n_in*/,
                              void* d_out, int /*out_size*/) {
    const float* x    = (const float*)d_in[0];
    const float* Wp   = (const float*)d_in[1];
    const float* bp   = (const float*)d_in[2];
    const float* W1   = (const float*)d_in[3];
    const float* b1   = (const float*)d_in[4];
    const float* W2   = (const float*)d_in[5];
    const float* b2   = (const float*)d_in[6];
    const float* W3   = (const float*)d_in[7];
    const float* b3   = (const float*)d_in[8];
    const float* Wb1  = (const float*)d_in[9];
    const float* bb1  = (const float*)d_in[10];
    const float* Wb2  = (const float*)d_in[11];
    const float* bb2  = (const float*)d_in[12];
    const float* Wb3  = (const float*)d_in[13];
    const float* bb3  = (const float*)d_in[14];
    const float* Wfc1 = (const float*)d_in[15];
    const float* bfc1 = (const float*)d_in[16];
    const float* Wfc2 = (const float*)d_in[17];
    const float* bfc2 = (const float*)d_in[18];
    float* out = (float*)d_out;

    float *basep, *h1p, *h2p, *h3p, *zp, *f1p, *f2p, *fc1p;
    float *W1tp, *W2tp, *W3tp, *Wp0p, *Wp1p, *zerop;
    cudaGetSymbolAddress((void**)&basep, g_base);
    cudaGetSymbolAddress((void**)&h1p,   g_h1);
    cudaGetSymbolAddress((void**)&h2p,   g_h2);
    cudaGetSymbolAddress((void**)&h3p,   g_h3);
    cudaGetSymbolAddress((void**)&zp,    g_z);
    cudaGetSymbolAddress((void**)&f1p,   g_f1);
    cudaGetSymbolAddress((void**)&f2p,   g_f2);
    cudaGetSymbolAddress((void**)&fc1p,  g_fc1);
    cudaGetSymbolAddress((void**)&W1tp,  g_W1t);
    cudaGetSymbolAddress((void**)&W2tp,  g_W2t);
    cudaGetSymbolAddress((void**)&W3tp,  g_W3t);
    cudaGetSymbolAddress((void**)&Wp0p,  g_Wp0);
    cudaGetSymbolAddress((void**)&Wp1p,  g_Wp1);
    cudaGetSymbolAddress((void**)&zerop, g_zero);

    // weight prep
    extract_wp_kernel<<<16, 256>>>(Wp, Wp0p, Wp1p);
    reorder_w_kernel<<<(128 * 64 * 3 + 255) / 256, 256>>>(W1, W1tp, 128, 64, 3);
    reorder_w_kernel<<<(256 * 128 * 3 + 255) / 256, 256>>>(W2, W2tp, 256, 128, 3);
    reorder_w_kernel<<<(256 * 256 * 3 + 255) / 256, 256>>>(W3, W3tp, 256, 256, 3);

    // base[b,p] = x0 @ Wp0^T + bp   (M=2048, N=64, K=64)
    gemm_kernel<128, 64, 16, 64, 64, 1, 64, 1, 0, 1, 16384, 64,
                false, false, false>
        <<<dim3(BATCH / 128, 1), 256>>>(x, Wp0p, bp, nullptr, basep);

    // patch: h1[b,c,p] = relu(base[b,p] + x[b,(c+1)*64:] @ Wp1^T)
    // M = 2048*255, N=64, K=64 ; inpos = c + 1 via PADL = -1
    gemm_kernel<128, 64, 16, 64, 64, 256, 64, 1, -1, 255, 16384, 255 * 64,
                true, false, true>
        <<<dim3(BATCH * 255 / 128, 1), 256>>>(x, Wp1p, zerop, basep, h1p);

    // branch MLP: f1 = relu(x0 @ Wb1^T + bb1)   (N=64, K=64)
    gemm_kernel<128, 64, 16, 64, 64, 1, 64, 1, 0, 1, 16384, 64,
                true, false, false>
        <<<dim3(BATCH / 128, 1), 256>>>(x, Wb1, bb1, nullptr, f1p);
    // f2 = relu(f1 @ Wb2^T + bb2)  (N=128, K=64)
    gemm_kernel<128, 128, 16, 128, 64, 1, 64, 1, 0, 1, 64, 128,
                true, false, false>
        <<<dim3(BATCH / 128, 1), 256>>>(f1p, Wb2, bb2, nullptr, f2p);
    // f3 = relu(f2 @ Wb3^T + bb3)  (N=256, K=128) -> tail of concat buffer
    gemm_kernel<128, 128, 16, 256, 128, 1, 128, 1, 0, 1, 128, 16640,
                true, false, false>
        <<<dim3(BATCH / 128, 2), 256>>>(f2p, Wb3, bb3, nullptr, zp + 16384);

    // conv1: (B,64,255) -> (B,128,255), s1 p1  (M=522240, N=128, K=192)
    gemm_kernel<128, 128, 16, 128, 192, 255, 64, 1, 1, 255, 255 * 64, 255 * 128,
                true, false, false>
        <<<dim3(BATCH * 255 / 128, 1), 256>>>(h1p, W1tp, b1, nullptr, h2p);

    // conv2: (B,128,255) -> (B,256,128), s2 p1  (M=262144, N=256, K=384)
    gemm_kernel<128, 128, 16, 256, 384, 255, 128, 2, 1, 128, 255 * 128, 128 * 256,
                true, false, false>
        <<<dim3(BATCH * 128 / 128, 2), 256>>>(h2p, W2tp, b2, nullptr, h3p);

    // conv3: (B,256,128) -> (B,256,64), s2 p1, transposed store into concat
    // (M=131072, N=256, K=768) ; z[b, n*64 + c]
    gemm_kernel<128, 128, 16, 256, 768, 128, 256, 2, 1, 64, 128 * 256, 16640,
                true, true, false>
        <<<dim3(BATCH * 64 / 128, 2), 256>>>(h3p, W3tp, b3, nullptr, zp);

    // fc1: relu(z @ Wfc1^T + bfc1)  (M=2048, N=1024, K=16640)
    gemm_kernel<128, 64, 16, 1024, 16640, 1, 16640, 1, 0, 1, 16640, 1024,
                true, false, false>
        <<<dim3(BATCH / 128, 16), 256>>>(zp, Wfc1, bfc1, nullptr, fc1p);

    // fc2: (B,1024) @ (2,1024)^T + bfc2
    fc2_kernel<<<BATCH, 256>>>(fc1p, Wfc2, bfc2, out);
}

// round 17
// speedup vs baseline: 1.0983x; 1.0983x over previous
#include <cuda_runtime.h>
#include <cstdint>

// ---------------------------------------------------------------------------
// CNN3_FPB: patch-GEMM -> 3x conv1d (im2col GEMM) -> FC, plus branch MLP.
// Big stages: 3xTF32 tensor-core im2col GEMM (mma.sync m16n8k8, fp32-accurate
// via hi/lo split). Small stages: verified fp32 SGEMM. Both use the
// register-staged double-buffered smem pipeline (1 barrier per k-tile).
// Activations stored [b][pos][ch] so im2col gathers are contiguous.
// ---------------------------------------------------------------------------

#define BATCH 2048

// scratch (device globals: allocation-free per harness rules)
__device__ float g_base[BATCH * 64];
__device__ float g_h1[(size_t)BATCH * 255 * 64];    // patch out, [b][pos][64]
__device__ float g_h2[(size_t)BATCH * 255 * 128];   // conv1 out, [b][pos][128]
__device__ float g_h3[(size_t)BATCH * 128 * 256];   // conv2 out, [b][pos][256]
__device__ float g_z[(size_t)BATCH * 16640];        // concat: conv3 (ch-major 16384) + f (256)
__device__ float g_f1[BATCH * 64];
__device__ float g_f2[BATCH * 128];
__device__ float g_fc1[(size_t)BATCH * 1024];
__device__ float g_W1t[128 * 192];
__device__ float g_W2t[256 * 384];
__device__ float g_W3t[256 * 768];
__device__ float g_Wp0[64 * 64];
__device__ float g_Wp1[64 * 64];
__device__ float g_zero[1024];                       // stays zero

// ---------------------------------------------------------------------------
__global__ void reorder_w_kernel(const float* __restrict__ W, float* __restrict__ Wt,
                                 int Cout, int Cin, int Kw) {
    int idx = blockIdx.x * blockDim.x + threadIdx.x;
    int total = Cout * Cin * Kw;
    if (idx >= total) return;
    int kp = idx % Kw;
    int ci = (idx / Kw) % Cin;
    int o  = idx / (Kw * Cin);
    Wt[(size_t)o * (Cin * Kw) + kp * Cin + ci] = W[idx];
}

__global__ void extract_wp_kernel(const float* __restrict__ Wp,
                                  float* __restrict__ W0, float* __restrict__ W1) {
    int idx = blockIdx.x * blockDim.x + threadIdx.x;
    if (idx >= 64 * 64) return;
    W0[idx] = Wp[idx * 2 + 0];
    W1[idx] = Wp[idx * 2 + 1];
}

// ---------------------------------------------------------------------------
// TF32 helpers
// ---------------------------------------------------------------------------
__device__ __forceinline__ void split_tf32(float x, uint32_t& hi, uint32_t& lo) {
    asm("cvt.rna.tf32.f32 %0, %1;" : "=r"(hi) : "f"(x));
    float hif = __uint_as_float(hi);
    asm("cvt.rna.tf32.f32 %0, %1;" : "=r"(lo) : "f"(x - hif));
}

__device__ __forceinline__ void mma_tf32(float* d, const uint32_t* a, const uint32_t* b) {
    asm volatile(
        "mma.sync.aligned.m16n8k8.row.col.f32.tf32.tf32.f32 "
        "{%0,%1,%2,%3}, {%4,%5,%6,%7}, {%8,%9}, {%0,%1,%2,%3};\n"
        : "+f"(d[0]), "+f"(d[1]), "+f"(d[2]), "+f"(d[3])
        : "r"(a[0]), "r"(a[1]), "r"(a[2]), "r"(a[3]), "r"(b[0]), "r"(b[1]));
}

// ---------------------------------------------------------------------------
// Tensor-core im2col GEMM (3xTF32). BM=128, BN=64, BK=16, 256 threads.
// 8 warps in 4(m) x 2(n); warp tile 32x32 = 2 m-atoms x 4 n-atoms (m16n8k8).
// Same im2col fetch + 2-stage reg-staged smem pipeline as the fp32 kernel.
// Smem pad +8 -> fragment LDS bank = (8t + g) mod 32, conflict-free.
// ---------------------------------------------------------------------------
template<int BM, int BN, int BK, int N, int K, int LIN, int CIN,
         int STRIDE, int PADL, int LOUT, int IN_STRIDE, int OUT_STRIDE,
         bool RELU, bool TRANS_STORE, bool HAS_ROWBIAS>
__global__ __launch_bounds__(256)
void gemm_tf32_kernel(const float* __restrict__ A,
                      const float* __restrict__ Wt,
                      const float* __restrict__ bias,
                      const float* __restrict__ rowbias,
                      float* __restrict__ out)
{
    constexpr int KV = BK / 4;
    constexpr int AIT = (BM * KV) / 256;
    constexpr int BIT = (BN * KV) / 256;
    constexpr int NT = K / BK;
    static_assert(BM == 128 && BN == 64 && BK == 16, "tensor tile config");
    static_assert(CIN % 4 == 0 && K % BK == 0, "vec/tiling preconds");
    __shared__ float As[2][BK][BM + 8];
    __shared__ float Bs[2][BK][BN + 8];
    const int tid = threadIdx.x;
    const int m0 = blockIdx.x * BM;
    const int n0 = blockIdx.y * BN;
    const int wid = tid >> 5, lane = tid & 31;
    const int g = lane >> 2, t = lane & 3;
    const int warp_m = wid >> 1, warp_n = wid & 1;
    const int mb = warp_m * 32, nb = warp_n * 32;

    float4 aReg[AIT], bReg[BIT];

    auto fetchA = [&](int k0) {
#pragma unroll
        for (int it = 0; it < AIT; it++) {
            int v = it * 256 + tid;
            int mm = v / KV;
            int kk = (v - mm * KV) * 4;
            int row = m0 + mm;
            int b = row / LOUT;
            int c = row - b * LOUT;
            int k = k0 + kk;
            int kpos = k / CIN;
            int ci = k - kpos * CIN;
            int inpos = c * STRIDE - PADL + kpos;
            float4 val = make_float4(0.f, 0.f, 0.f, 0.f);
            if (inpos >= 0 && inpos < LIN)
                val = *reinterpret_cast<const float4*>(
                    &A[(size_t)b * IN_STRIDE + (size_t)inpos * CIN + ci]);
            aReg[it] = val;
        }
    };
    auto fetchB = [&](int k0) {
#pragma unroll
        for (int it = 0; it < BIT; it++) {
            int v = it * 256 + tid;
            int nn = v / KV;
            int kk = (v - nn * KV) * 4;
            bReg[it] = *reinterpret_cast<const float4*>(
                &Wt[(size_t)(n0 + nn) * K + (k0 + kk)]);
        }
    };
    auto stageStore = [&](int s) {
#pragma unroll
        for (int it = 0; it < AIT; it++) {
            int v = it * 256 + tid;
            int mm = v / KV;
            int kk = (v - mm * KV) * 4;
            As[s][kk + 0][mm] = aReg[it].x;
            As[s][kk + 1][mm] = aReg[it].y;
            As[s][kk + 2][mm] = aReg[it].z;
            As[s][kk + 3][mm] = aReg[it].w;
        }
#pragma unroll
        for (int it = 0; it < BIT; it++) {
            int v = it * 256 + tid;
            int nn = v / KV;
            int kk = (v - nn * KV) * 4;
            Bs[s][kk + 0][nn] = bReg[it].x;
            Bs[s][kk + 1][nn] = bReg[it].y;
            Bs[s][kk + 2][nn] = bReg[it].z;
            Bs[s][kk + 3][nn] = bReg[it].w;
        }
    };

    float acc[2][4][4];
#pragma unroll
    for (int ma = 0; ma < 2; ma++)
#pragma unroll
        for (int na = 0; na < 4; na++)
#pragma unroll
            for (int r = 0; r < 4; r++) acc[ma][na][r] = 0.f;

    fetchA(0);
    fetchB(0);
    stageStore(0);
    __syncthreads();

    int cur = 0;
    for (int tt = 0; tt < NT; tt++) {
        if (tt + 1 < NT) {
            fetchA((tt + 1) * BK);
            fetchB((tt + 1) * BK);
        }
#pragma unroll
        for (int ks = 0; ks < BK; ks += 8) {
            uint32_t aHi[2][4], aLo[2][4], bHi[4][2], bLo[4][2];
#pragma unroll
            for (int ma = 0; ma < 2; ma++) {
                int r0 = mb + ma * 16;
                float v0 = As[cur][ks + t][r0 + g];
                float v1 = As[cur][ks + t][r0 + g + 8];
                float v2 = As[cur][ks + t + 4][r0 + g];
                float v3 = As[cur][ks + t + 4][r0 + g + 8];
                split_tf32(v0, aHi[ma][0], aLo[ma][0]);
                split_tf32(v1, aHi[ma][1], aLo[ma][1]);
                split_tf32(v2, aHi[ma][2], aLo[ma][2]);
                split_tf32(v3, aHi[ma][3], aLo[ma][3]);
            }
#pragma unroll
            for (int na = 0; na < 4; na++) {
                int c0 = nb + na * 8 + g;
                float w0 = Bs[cur][ks + t][c0];
                float w1 = Bs[cur][ks + t + 4][c0];
                split_tf32(w0, bHi[na][0], bLo[na][0]);
                split_tf32(w1, bHi[na][1], bLo[na][1]);
            }
#pragma unroll
            for (int ma = 0; ma < 2; ma++)
#pragma unroll
                for (int na = 0; na < 4; na++) {
                    mma_tf32(acc[ma][na], aLo[ma], bHi[na]);
                    mma_tf32(acc[ma][na], aHi[ma], bLo[na]);
                    mma_tf32(acc[ma][na], aHi[ma], bHi[na]);
                }
        }
        if (tt + 1 < NT) {
            stageStore(cur ^ 1);
            __syncthreads();
            cur ^= 1;
        }
    }

    // epilogue: D regs map (g,2t),(g,2t+1),(g+8,2t),(g+8,2t+1)
#pragma unroll
    for (int ma = 0; ma < 2; ma++) {
#pragma unroll
        for (int half = 0; half < 2; half++) {
            int row = m0 + mb + ma * 16 + g + half * 8;
            int b = row / LOUT;
            int c = row - b * LOUT;
#pragma unroll
            for (int na = 0; na < 4; na++) {
                int n = n0 + nb + na * 8 + 2 * t;
                float v0 = acc[ma][na][half * 2 + 0] + bias[n];
                float v1 = acc[ma][na][half * 2 + 1] + bias[n + 1];
                if (HAS_ROWBIAS) {
                    v0 += rowbias[b * N + n];
                    v1 += rowbias[b * N + n + 1];
                }
                if (RELU) { v0 = fmaxf(v0, 0.f); v1 = fmaxf(v1, 0.f); }
                if (TRANS_STORE) {
                    out[(size_t)b * OUT_STRIDE + (size_t)n * LOUT + c] = v0;
                    out[(size_t)b * OUT_STRIDE + (size_t)(n + 1) * LOUT + c] = v1;
                } else {
                    out[(size_t)b * OUT_STRIDE + (size_t)c * N + n] = v0;
                    out[(size_t)b * OUT_STRIDE + (size_t)c * N + n + 1] = v1;
                }
            }
        }
    }
}

// ---------------------------------------------------------------------------
// fp32 SGEMM (verified) for small stages.
// ---------------------------------------------------------------------------
template<int BM, int BN, int BK, int N, int K, int LIN, int CIN,
         int STRIDE, int PADL, int LOUT, int IN_STRIDE, int OUT_STRIDE,
         bool RELU, bool TRANS_STORE, bool HAS_ROWBIAS>
__global__ __launch_bounds__(256, 2)
void gemm_kernel(const float* __restrict__ A,
                 const float* __restrict__ Wt,
                 const float* __restrict__ bias,
                 const float* __restrict__ rowbias,
                 float* __restrict__ out)
{
    constexpr int TM = BM / 16, TN = BN / 16;
    constexpr int KV = BK / 4;
    constexpr int AIT = (BM * KV) / 256;
    constexpr int BIT = (BN * KV) / 256;
    constexpr int NT = K / BK;
    static_assert(CIN % 4 == 0 && K % 4 == 0 && BK % 4 == 0, "vec preconds");
    static_assert(TM % 4 == 0 && TN % 4 == 0, "frag vec preconds");
    static_assert((BM * KV) % 256 == 0 && (BN * KV) % 256 == 0, "tile loop preconds");
    static_assert(K % BK == 0, "k tiling");
    __shared__ float As[2][BK][BM + 4];
    __shared__ float Bs[2][BK][BN + 4];
    const int tid = threadIdx.x;
    const int ty = tid >> 4, tx = tid & 15;
    const int m0 = blockIdx.x * BM;
    const int n0 = blockIdx.y * BN;

    float4 aReg[AIT], bReg[BIT];

    auto fetchA = [&](int k0) {
#pragma unroll
        for (int it = 0; it < AIT; it++) {
            int v = it * 256 + tid;
            int mm = v / KV;
            int kk = (v - mm * KV) * 4;
            int row = m0 + mm;
            int b = row / LOUT;
            int c = row - b * LOUT;
            int k = k0 + kk;
            int kpos = k / CIN;
            int ci = k - kpos * CIN;
            int inpos = c * STRIDE - PADL + kpos;
            float4 val = make_float4(0.f, 0.f, 0.f, 0.f);
            if (inpos >= 0 && inpos < LIN)
                val = *reinterpret_cast<const float4*>(
                    &A[(size_t)b * IN_STRIDE + (size_t)inpos * CIN + ci]);
            aReg[it] = val;
        }
    };
    auto fetchB = [&](int k0) {
#pragma unroll
        for (int it = 0; it < BIT; it++) {
            int v = it * 256 + tid;
            int nn = v / KV;
            int kk = (v - nn * KV) * 4;
            bReg[it] = *reinterpret_cast<const float4*>(
                &Wt[(size_t)(n0 + nn) * K + (k0 + kk)]);
        }
    };
    auto stageStore = [&](int s) {
#pragma unroll
        for (int it = 0; it < AIT; it++) {
            int v = it * 256 + tid;
            int mm = v / KV;
            int kk = (v - mm * KV) * 4;
            As[s][kk + 0][mm] = aReg[it].x;
            As[s][kk + 1][mm] = aReg[it].y;
            As[s][kk + 2][mm] = aReg[it].z;
            As[s][kk + 3][mm] = aReg[it].w;
        }
#pragma unroll
        for (int it = 0; it < BIT; it++) {
            int v = it * 256 + tid;
            int nn = v / KV;
            int kk = (v - nn * KV) * 4;
            Bs[s][kk + 0][nn] = bReg[it].x;
            Bs[s][kk + 1][nn] = bReg[it].y;
            Bs[s][kk + 2][nn] = bReg[it].z;
            Bs[s][kk + 3][nn] = bReg[it].w;
        }
    };

    float acc[TM][TN];
#pragma unroll
    for (int i = 0; i < TM; i++)
#pragma unroll
        for (int j = 0; j < TN; j++) acc[i][j] = 0.f;

    fetchA(0);
    fetchB(0);
    stageStore(0);
    __syncthreads();

    int cur = 0;
    for (int t = 0; t < NT; t++) {
        if (t + 1 < NT) {
            fetchA((t + 1) * BK);
            fetchB((t + 1) * BK);
        }
#pragma unroll
        for (int kk = 0; kk < BK; kk++) {
            float a[TM], bb[TN];
#pragma unroll
            for (int i = 0; i < TM; i += 4)
                *reinterpret_cast<float4*>(&a[i]) =
                    *reinterpret_cast<const float4*>(&As[cur][kk][ty * TM + i]);
#pragma unroll
            for (int j = 0; j < TN; j += 4)
                *reinterpret_cast<float4*>(&bb[j]) =
                    *reinterpret_cast<const float4*>(&Bs[cur][kk][tx * TN + j]);
#pragma unroll
            for (int i = 0; i < TM; i++)
#pragma unroll
                for (int j = 0; j < TN; j++)
                    acc[i][j] = fmaf(a[i], bb[j], acc[i][j]);
        }
        if (t + 1 < NT) {
            stageStore(cur ^ 1);
            __syncthreads();
            cur ^= 1;
        }
    }

#pragma unroll
    for (int i = 0; i < TM; i++) {
        int row = m0 + ty * TM + i;
        int b = row / LOUT;
        int c = row - b * LOUT;
#pragma unroll
        for (int j = 0; j < TN; j++) {
            int n = n0 + tx * TN + j;
            float v = acc[i][j] + bias[n];
            if (HAS_ROWBIAS) v += rowbias[b * N + n];
            if (RELU) v = fmaxf(v, 0.f);
            if (TRANS_STORE)
                out[(size_t)b * OUT_STRIDE + (size_t)n * LOUT + c] = v;
            else
                out[(size_t)b * OUT_STRIDE + (size_t)c * N + n] = v;
        }
    }
}

// ---------------------------------------------------------------------------
// FC2: (B,1024) @ (2,1024)^T + b -> (B,2).
// ---------------------------------------------------------------------------
__global__ __launch_bounds__(256)
void fc2_kernel(const float* __restrict__ in, const float* __restrict__ W,
                const float* __restrict__ bias, float* __restrict__ out) {
    int b = blockIdx.x;
    float a0 = 0.f, a1 = 0.f;
    for (int k = threadIdx.x * 4; k < 1024; k += 256 * 4) {
        float4 v = *reinterpret_cast<const float4*>(&in[(size_t)b * 1024 + k]);
        float4 w0 = *reinterpret_cast<const float4*>(&W[k]);
        float4 w1 = *reinterpret_cast<const float4*>(&W[1024 + k]);
        a0 = fmaf(v.x, w0.x, fmaf(v.y, w0.y, fmaf(v.z, w0.z, fmaf(v.w, w0.w, a0))));
        a1 = fmaf(v.x, w1.x, fmaf(v.y, w1.y, fmaf(v.z, w1.z, fmaf(v.w, w1.w, a1))));
    }
#pragma unroll
    for (int off = 16; off > 0; off >>= 1) {
        a0 += __shfl_xor_sync(0xFFFFFFFFu, a0, off);
        a1 += __shfl_xor_sync(0xFFFFFFFFu, a1, off);
    }
    __shared__ float s0[8], s1[8];
    int wid = threadIdx.x >> 5, lid = threadIdx.x & 31;
    if (lid == 0) { s0[wid] = a0; s1[wid] = a1; }
    __syncthreads();
    if (threadIdx.x == 0) {
        float t0 = 0.f, t1 = 0.f;
#pragma unroll
        for (int w = 0; w < 8; w++) { t0 += s0[w]; t1 += s1[w]; }
        out[b * 2 + 0] = t0 + bias[0];
        out[b * 2 + 1] = t1 + bias[1];
    }
}

// ---------------------------------------------------------------------------
extern "C" void kernel_launch(void* const* d_in, const int* /*in_sizes*/, int /*n_in*/,
                              void* d_out, int /*out_size*/) {
    const float* x    = (const float*)d_in[0];
    const float* Wp   = (const float*)d_in[1];
    const float* bp   = (const float*)d_in[2];
    const float* W1   = (const float*)d_in[3];
    const float* b1   = (const float*)d_in[4];
    const float* W2   = (const float*)d_in[5];
    const float* b2   = (const float*)d_in[6];
    const float* W3   = (const float*)d_in[7];
    const float* b3   = (const float*)d_in[8];
    const float* Wb1  = (const float*)d_in[9];
    const float* bb1  = (const float*)d_in[10];
    const float* Wb2  = (const float*)d_in[11];
    const float* bb2  = (const float*)d_in[12];
    const float* Wb3  = (const float*)d_in[13];
    const float* bb3  = (const float*)d_in[14];
    const float* Wfc1 = (const float*)d_in[15];
    const float* bfc1 = (const float*)d_in[16];
    const float* Wfc2 = (const float*)d_in[17];
    const float* bfc2 = (const float*)d_in[18];
    float* out = (float*)d_out;

    float *basep, *h1p, *h2p, *h3p, *zp, *f1p, *f2p, *fc1p;
    float *W1tp, *W2tp, *W3tp, *Wp0p, *Wp1p, *zerop;
    cudaGetSymbolAddress((void**)&basep, g_base);
    cudaGetSymbolAddress((void**)&h1p,   g_h1);
    cudaGetSymbolAddress((void**)&h2p,   g_h2);
    cudaGetSymbolAddress((void**)&h3p,   g_h3);
    cudaGetSymbolAddress((void**)&zp,    g_z);
    cudaGetSymbolAddress((void**)&f1p,   g_f1);
    cudaGetSymbolAddress((void**)&f2p,   g_f2);
    cudaGetSymbolAddress((void**)&fc1p,  g_fc1);
    cudaGetSymbolAddress((void**)&W1tp,  g_W1t);
    cudaGetSymbolAddress((void**)&W2tp,  g_W2t);
    cudaGetSymbolAddress((void**)&W3tp,  g_W3t);
    cudaGetSymbolAddress((void**)&Wp0p,  g_Wp0);
    cudaGetSymbolAddress((void**)&Wp1p,  g_Wp1);
    cudaGetSymbolAddress((void**)&zerop, g_zero);

    // weight prep
    extract_wp_kernel<<<16, 256>>>(Wp, Wp0p, Wp1p);
    reorder_w_kernel<<<(128 * 64 * 3 + 255) / 256, 256>>>(W1, W1tp, 128, 64, 3);
    reorder_w_kernel<<<(256 * 128 * 3 + 255) / 256, 256>>>(W2, W2tp, 256, 128, 3);
    reorder_w_kernel<<<(256 * 256 * 3 + 255) / 256, 256>>>(W3, W3tp, 256, 256, 3);

    // base[b,p] = x0 @ Wp0^T + bp   (fp32; M=2048, N=64, K=64)
    gemm_kernel<128, 64, 16, 64, 64, 1, 64, 1, 0, 1, 16384, 64,
                false, false, false>
        <<<dim3(BATCH / 128, 1), 256>>>(x, Wp0p, bp, nullptr, basep);

    // patch (TENSOR): h1 = relu(base + x[:, (c+1)*64:] @ Wp1^T)
    gemm_tf32_kernel<128, 64, 16, 64, 64, 256, 64, 1, -1, 255, 16384, 255 * 64,
                     true, false, true>
        <<<dim3(BATCH * 255 / 128, 1), 256>>>(x, Wp1p, zerop, basep, h1p);

    // branch MLP (fp32, tiny)
    gemm_kernel<128, 64, 16, 64, 64, 1, 64, 1, 0, 1, 16384, 64,
                true, false, false>
        <<<dim3(BATCH / 128, 1), 256>>>(x, Wb1, bb1, nullptr, f1p);
    gemm_kernel<128, 128, 16, 128, 64, 1, 64, 1, 0, 1, 64, 128,
                true, false, false>
        <<<dim3(BATCH / 128, 1), 256>>>(f1p, Wb2, bb2, nullptr, f2p);
    gemm_kernel<128, 128, 16, 256, 128, 1, 128, 1, 0, 1, 128, 16640,
                true, false, false>
        <<<dim3(BATCH / 128, 2), 256>>>(f2p, Wb3, bb3, nullptr, zp + 16384);

    // conv1 (TENSOR): (B,64,255) -> (B,128,255), s1 p1
    gemm_tf32_kernel<128, 64, 16, 128, 192, 255, 64, 1, 1, 255, 255 * 64, 255 * 128,
                     true, false, false>
        <<<dim3(BATCH * 255 / 128, 2), 256>>>(h1p, W1tp, b1, nullptr, h2p);

    // conv2 (TENSOR): (B,128,255) -> (B,256,128), s2 p1
    gemm_tf32_kernel<128, 64, 16, 256, 384, 255, 128, 2, 1, 128, 255 * 128, 128 * 256,
                     true, false, false>
        <<<dim3(BATCH * 128 / 128, 4), 256>>>(h2p, W2tp, b2, nullptr, h3p);

    // conv3 (TENSOR): (B,256,128) -> (B,256,64), s2 p1, transposed concat store
    gemm_tf32_kernel<128, 64, 16, 256, 768, 128, 256, 2, 1, 64, 128 * 256, 16640,
                     true, true, false>
        <<<dim3(BATCH * 64 / 128, 4), 256>>>(h3p, W3tp, b3, nullptr, zp);

    // fc1 (TENSOR): relu(z @ Wfc1^T + bfc1)  (M=2048, N=1024, K=16640)
    gemm_tf32_kernel<128, 64, 16, 1024, 16640, 1, 16640, 1, 0, 1, 16640, 1024,
                     true, false, false>
        <<<dim3(BATCH / 128, 16), 256>>>(zp, Wfc1, bfc1, nullptr, fc1p);

    // fc2
    fc2_kernel<<<BATCH, 256>>>(fc1p, Wfc2, bfc2, out);
}